// round 15
// baseline (speedup 1.0000x reference)
#include <cuda_runtime.h>
#include <math.h>
#include <stdint.h>

#define NBATCH 64
#define NSTEP  1024
#define NIN    256
#define NH     512

// smem floats: wsm [3][32][512] swizzled | hsm [4][512] | part [16][384] | h_loc[2][128] | sync
#define WS_OFF   0
#define HS_OFF   (3*32*512)                 // 49152
#define PT_OFF   (HS_OFF + 4*512)           // 51200
#define HL_OFF   (PT_OFF + 16*384)          // 57344
#define SY_OFF   (HL_OFF + 256)             // 57600: done[32], dumpcnt[2], readdone[2]
#define SMEM_FLOATS (SY_OFF + 36)
#define SMEM_BYTES  (SMEM_FLOATS*4)         // 230,544 B

typedef unsigned long long u64;

#define FMA2(acc, a, b) asm("fma.rn.f32x2 %0, %1, %2, %0;" : "+l"(acc) : "l"(a), "l"(b))
#define DUP2(r, x)      asm("mov.b64 %0, {%1, %1};" : "=l"(r) : "f"(x))
#define UNPACK2(lo, hi, v) asm("mov.b64 {%0, %1}, %2;" : "=f"(lo), "=f"(hi) : "l"(v))

__device__ float    g_x[(size_t)3*NBATCH*NSTEP*NH];   // input projections
__device__ float    g_h[2*NBATCH*NH];
__device__ unsigned g_flags[256];                      // [16 groups][16 jt]

__device__ __forceinline__ unsigned ld_acq(const unsigned* p) {
  unsigned v;
  asm volatile("ld.global.acquire.gpu.b32 %0, [%1];" : "=r"(v) : "l"(p) : "memory");
  return v;
}
__device__ __forceinline__ void st_rel(unsigned* p, unsigned v) {
  asm volatile("st.global.release.gpu.b32 [%0], %1;" :: "l"(p), "r"(v) : "memory");
}
__device__ __forceinline__ unsigned ld_acq_sh(const unsigned* p) {
  unsigned v;
  asm volatile("ld.acquire.cta.b32 %0, [%1];" : "=r"(v) : "l"(p) : "memory");
  return v;
}
__device__ __forceinline__ void st_rel_sh(unsigned* p, unsigned v) {
  asm volatile("st.release.cta.b32 [%0], %1;" :: "l"(p), "r"(v) : "memory");
}
__device__ __forceinline__ void red_rel_add_sh(unsigned* p, unsigned v) {
  asm volatile("red.release.cta.add.u32 [%0], %1;" :: "l"(p), "r"(v) : "memory");
}

// ---------------- input projection GEMM ----------------
__global__ void __launch_bounds__(256) xproj_kernel(
    const float* __restrict__ A,
    const float* __restrict__ w0, const float* __restrict__ w1, const float* __restrict__ w2,
    const float* __restrict__ b0, const float* __restrict__ b1, const float* __restrict__ b2)
{
  __shared__ float As[32][68];
  __shared__ float Bs[32][68];

  int tid = threadIdx.x;
  if (blockIdx.x == 0 && blockIdx.y == 0 && blockIdx.z == 0)
    g_flags[tid] = 0u;

  int g = blockIdx.z;
  const float* W    = (g==0) ? w0 : ((g==1) ? w1 : w2);
  const float* bias = (g==0) ? b0 : ((g==1) ? b1 : b2);
  float* C = g_x + (size_t)g * (size_t)(NBATCH*NSTEP) * NH;

  int m0 = blockIdx.y * 64;
  int n0 = blockIdx.x * 64;
  int tx = tid & 15, ty = tid >> 4;
  int lr = tid >> 3;
  int lc = (tid & 7) * 4;

  u64 acc2[4][2] = {};

  for (int k0 = 0; k0 < NIN; k0 += 32) {
    float4 a0 = *(const float4*)(A + (size_t)(m0+lr   )*NIN + k0 + lc);
    float4 a1 = *(const float4*)(A + (size_t)(m0+lr+32)*NIN + k0 + lc);
    float4 v0 = *(const float4*)(W + (size_t)(n0+lr   )*NIN + k0 + lc);
    float4 v1 = *(const float4*)(W + (size_t)(n0+lr+32)*NIN + k0 + lc);
    __syncthreads();
    As[lc+0][lr] = a0.x; As[lc+1][lr] = a0.y; As[lc+2][lr] = a0.z; As[lc+3][lr] = a0.w;
    As[lc+0][lr+32] = a1.x; As[lc+1][lr+32] = a1.y; As[lc+2][lr+32] = a1.z; As[lc+3][lr+32] = a1.w;
    Bs[lc+0][lr] = v0.x; Bs[lc+1][lr] = v0.y; Bs[lc+2][lr] = v0.z; Bs[lc+3][lr] = v0.w;
    Bs[lc+0][lr+32] = v1.x; Bs[lc+1][lr+32] = v1.y; Bs[lc+2][lr+32] = v1.z; Bs[lc+3][lr+32] = v1.w;
    __syncthreads();
    #pragma unroll
    for (int kk = 0; kk < 32; kk++) {
      float4 av = *(const float4*)(&As[kk][ty*4]);
      ulonglong2 bp = *(const ulonglong2*)(&Bs[kk][tx*4]);
      u64 d0, d1, d2, d3;
      DUP2(d0, av.x); DUP2(d1, av.y); DUP2(d2, av.z); DUP2(d3, av.w);
      FMA2(acc2[0][0], d0, bp.x); FMA2(acc2[0][1], d0, bp.y);
      FMA2(acc2[1][0], d1, bp.x); FMA2(acc2[1][1], d1, bp.y);
      FMA2(acc2[2][0], d2, bp.x); FMA2(acc2[2][1], d2, bp.y);
      FMA2(acc2[3][0], d3, bp.x); FMA2(acc2[3][1], d3, bp.y);
    }
  }

  float4 bv = *(const float4*)(bias + n0 + tx*4);
  #pragma unroll
  for (int i = 0; i < 4; i++) {
    int row = m0 + ty*4 + i;
    float c0, c1, c2, c3;
    UNPACK2(c0, c1, acc2[i][0]);
    UNPACK2(c2, c3, acc2[i][1]);
    float4 o;
    o.x = c0 + bv.x; o.y = c1 + bv.y;
    o.z = c2 + bv.z; o.w = c3 + bv.w;
    *(float4*)(C + (size_t)row*NH + n0 + tx*4) = o;
  }
}

// ---- persistent GRU: 2 interleaved chains, flag-gated part buffer, free-running warps ----
// 128 CTAs = 16 j-tiles x 8 CTA-rows (m). Chains gA=2m, gB=2m+1 (4 batches each).
// part use-sequence: A(t)dump -> A(t)read -> B(t)dump -> B(t)read -> A(t+1)dump ...
//   dump A(t) gates on readdone[1] >= t; dump B(t) gates on readdone[0] >= t+1.
//   epilogue(c,t) gates on dumpcnt[c] == 16*(t+1) (warps red.release +1 after dump).
// Epilogue duty rotates by parity: even t -> warps 8..15 (A:8-11, B:12-15);
// odd t -> warps 0..7 (A:0-3, B:4-7). hprev hands off via smem h_loc (ordering rides
// the release chains: epi(t-1) stores h_loc before flag release; dumpers acquire the
// flag; epi(t) acquires dumpcnt released by dumpers).
// 544 threads: warps 0..15 workers (k-split 16), warp 16 = L2 flag poller.
__global__ void __launch_bounds__(544, 1) gru_rec(
    const float* __restrict__ h0,
    const float* __restrict__ w_hr, const float* __restrict__ w_hz, const float* __restrict__ w_hn,
    const float* __restrict__ b_hr, const float* __restrict__ b_hz, const float* __restrict__ b_hn,
    float* __restrict__ out, int write_hlast)
{
  extern __shared__ float sm[];
  float* wsm   = sm + WS_OFF;                // [3][32][512], float4-XOR swizzled
  float* hsm   = sm + HS_OFF;                // [4][512] warp-private columns
  float* part  = sm + PT_OFF;                // [16][384]
  float* h_loc = sm + HL_OFF;                // [2][128]
  unsigned* done     = (unsigned*)(sm + SY_OFF);        // [2][16]
  unsigned* dumpcnt  = (unsigned*)(sm + SY_OFF + 32);   // [2]
  unsigned* readdone = (unsigned*)(sm + SY_OFF + 34);   // [2]

  int tid  = threadIdx.x;
  int r    = tid >> 5;                 // 0..15 worker k-split; 16 = poller
  int jl   = tid & 31;
  int m    = blockIdx.x >> 4;          // 0..7
  int jt   = blockIdx.x & 15;
  int j    = jt*32 + jl;
  int k0   = r*32;
  int sw   = (jl & 7);

  if (tid < 512) {
    const float* srcs[3] = {w_hr, w_hz, w_hn};
    #pragma unroll
    for (int g = 0; g < 3; g++) {
      const float* wsrc = srcs[g] + (size_t)j*NH;
      float* wdst = wsm + (g*32 + jl)*512;
      #pragma unroll
      for (int kk = 0; kk < 32; kk += 4) {
        int k16 = (k0 + kk) >> 2;
        *(float4*)(wdst + ((k16 ^ sw) << 2)) = *(const float4*)(wsrc + k0 + kk);
      }
    }
  }
  if (tid < 32) done[tid] = 0u;
  if (tid == 0) { dumpcnt[0] = 0u; dumpcnt[1] = 0u; readdone[0] = 0u; readdone[1] = 0u; }
  if (tid < 256) {  // seed h_loc from h0
    int c = tid >> 7, s = tid & 127;
    h_loc[c*128 + s] = h0[(size_t)((2*m + c)*4 + (s >> 5))*NH + jt*32 + (s & 31)];
  }
  __syncthreads();

  // ---- poller warp ----
  if (r == 16) {
    if (jl < 32) {
      const unsigned* fp = g_flags + m*32 + jl;
      unsigned* dp = done + jl;
      unsigned last = 0u;
      while (last < (unsigned)NSTEP) {
        unsigned v = ld_acq(fp);
        if (v > last) { last = v; st_rel_sh(dp, v); }
      }
    }
    return;
  }

  // ---- workers ----
  float bhr = b_hr[j], bhz = b_hz[j], bhn = b_hn[j];
  const float* wr = wsm + (0*32 + jl)*512;
  const float* wz = wsm + (1*32 + jl)*512;
  const float* wn = wsm + (2*32 + jl)*512;

  // duty per parity: p=0 -> warps 8..15 (A:8-11 B:12-15); p=1 -> warps 0..7 (A:0-3 B:4-7)
  int dutyc[2], dutyeb[2], dutybar[2], dutylead[2];
  {
    // p = 0
    if (r >= 8 && r < 12)      { dutyc[0] = 0; dutyeb[0] = r - 8;  dutybar[0] = 2; dutylead[0] = (r == 8); }
    else if (r >= 12)          { dutyc[0] = 1; dutyeb[0] = r - 12; dutybar[0] = 3; dutylead[0] = (r == 12); }
    else                       { dutyc[0] = -1; dutyeb[0] = 0; dutybar[0] = 0; dutylead[0] = 0; }
    // p = 1
    if (r < 4)                 { dutyc[1] = 0; dutyeb[1] = r;      dutybar[1] = 4; dutylead[1] = (r == 0); }
    else if (r < 8)            { dutyc[1] = 1; dutyeb[1] = r - 4;  dutybar[1] = 5; dutylead[1] = (r == 4); }
    else                       { dutyc[1] = -1; dutyeb[1] = 0; dutybar[1] = 0; dutylead[1] = 0; }
  }
  // per-parity epilogue pointers
  const float *xq0[2], *xq1[2], *xq2[2];
  float *outq[2], *hlastq[2];
  unsigned* flagq[2];
  int ebbq[2];
  #pragma unroll
  for (int p = 0; p < 2; p++) {
    if (dutyc[p] >= 0) {
      int bb = (2*m + dutyc[p])*4 + dutyeb[p];
      ebbq[p] = bb;
      xq0[p] = g_x + (size_t)bb*NSTEP*NH + j;
      xq1[p] = xq0[p] + (size_t)NBATCH*NSTEP*NH;
      xq2[p] = xq1[p] + (size_t)NBATCH*NSTEP*NH;
      outq[p]  = out + (size_t)bb*NSTEP*NH + j;
      hlastq[p] = out + (size_t)NBATCH*NSTEP*NH + (size_t)bb*NH + j;
      flagq[p] = g_flags + m*32 + dutyc[p]*16 + jt;
    } else {
      ebbq[p] = 0; xq0[p] = xq1[p] = xq2[p] = 0; outq[p] = hlastq[p] = 0; flagq[p] = 0;
    }
  }

  int sb = jl >> 3, sc = jl & 7;
  int sidx = sb*128 + r*8 + sc;

  #pragma unroll 1
  for (int t = 0; t < NSTEP; t++) {
    int p = t & 1;
    // prefetch my duty's x contributions
    float xr = 0.f, xz = 0.f, xn = 0.f;
    if (dutyc[p] >= 0) {
      xr = __ldcs(xq0[p] + (size_t)t*NH);
      xz = __ldcs(xq1[p] + (size_t)t*NH);
      xn = __ldcs(xq2[p] + (size_t)t*NH);
    }

    #pragma unroll
    for (int c = 0; c < 2; c++) {
      // wait my chunk's producer flag
      if (t > 0) {
        const unsigned* dp = done + c*16 + r;
        while (ld_acq_sh(dp) < (unsigned)t) { }
      }
      // stage my chunk (warp-private columns)
      {
        const float4* src = (t == 0)
          ? (const float4*)(h0 + (size_t)(2*m + c)*4*NH)
          : (const float4*)(g_h + (size_t)((t-1)&1)*NBATCH*NH + (size_t)(2*m + c)*4*NH);
        ((float4*)hsm)[sidx] = __ldcg(src + sidx);
      }
      __syncwarp();

      // matvec: k in [k0, k0+32), 3 gates, 4 batches, packed fp32x2
      u64 ar2[4] = {}, az2[4] = {}, an2[4] = {};
      #pragma unroll
      for (int kk8 = 0; kk8 < 8; kk8++) {
        int s4 = ((r*8 + kk8) ^ sw) << 2;
        int k  = k0 + kk8*4;
        ulonglong2 vr = *(const ulonglong2*)(wr + s4);
        ulonglong2 vz = *(const ulonglong2*)(wz + s4);
        ulonglong2 vn = *(const ulonglong2*)(wn + s4);
        #pragma unroll
        for (int b = 0; b < 4; b++) {
          ulonglong2 hv = *(const ulonglong2*)(hsm + b*NH + k);
          FMA2(ar2[b], vr.x, hv.x); FMA2(ar2[b], vr.y, hv.y);
          FMA2(az2[b], vz.x, hv.x); FMA2(az2[b], vz.y, hv.y);
          FMA2(an2[b], vn.x, hv.x); FMA2(an2[b], vn.y, hv.y);
        }
      }
      float sr[4], sz[4], sn[4];
      #pragma unroll
      for (int b = 0; b < 4; b++) {
        float lo, hi;
        UNPACK2(lo, hi, ar2[b]); sr[b] = lo + hi;
        UNPACK2(lo, hi, az2[b]); sz[b] = lo + hi;
        UNPACK2(lo, hi, an2[b]); sn[b] = lo + hi;
      }

      // dump gate: previous part-use read must be complete
      if (c == 0) { while (ld_acq_sh(&readdone[1]) < (unsigned)t) { } }
      else        { while (ld_acq_sh(&readdone[0]) < (unsigned)(t+1)) { } }

      {
        int row = r*384;
        #pragma unroll
        for (int b = 0; b < 4; b++) {
          part[row +   0 + b*32 + jl] = sr[b];
          part[row + 128 + b*32 + jl] = sz[b];
          part[row + 256 + b*32 + jl] = sn[b];
        }
      }
      __syncwarp();
      if (jl == 0) red_rel_add_sh(&dumpcnt[c], 1u);

      // epilogue: only this chain's duty warps at this parity
      if (dutyc[p] == c) {
        while (ld_acq_sh(&dumpcnt[c]) < 16u*(unsigned)(t+1)) { }
        int et = dutyeb[p]*32 + jl;
        float Sr = 0.f, Sz = 0.f, Sn = 0.f;
        #pragma unroll
        for (int rr = 0; rr < 16; rr++) {
          Sr += part[rr*384 +       et];
          Sz += part[rr*384 + 128 + et];
          Sn += part[rr*384 + 256 + et];
        }
        float hprev = h_loc[c*128 + et];
        float rg = 1.f/(1.f + __expf(-(xr + Sr + bhr)));
        float zg = 1.f/(1.f + __expf(-(xz + Sz + bhz)));
        float ng = tanhf(xn + rg*(Sn + bhn));
        float hnew = (1.f - zg)*ng + zg*hprev;

        h_loc[c*128 + et] = hnew;
        __stcg(&g_h[(size_t)(t&1)*NBATCH*NH + (size_t)ebbq[p]*NH + j], hnew);

        // rendezvous among this duty group's 4 warps, then release
        asm volatile("bar.sync %0, 128;" :: "r"(dutybar[p]) : "memory");
        if (dutylead[p] && jl == 0) {
          st_rel(flagq[p], (unsigned)(t+1));
          st_rel_sh(done + c*16 + jt, (unsigned)(t+1));   // self-publish
          st_rel_sh(&readdone[c], (unsigned)(t+1));       // part free for next use
        }

        // non-critical stores after the release
        __stcs(outq[p] + (size_t)t*NH, hnew);
        if (write_hlast && t == NSTEP-1) hlastq[p][0] = hnew;
      }
    }
  }
}

extern "C" void kernel_launch(void* const* d_in, const int* in_sizes, int n_in,
                              void* d_out, int out_size) {
  const float* inp  = (const float*)d_in[0];
  const float* h0   = (const float*)d_in[1];
  const float* w_ir = (const float*)d_in[2];
  const float* w_iz = (const float*)d_in[3];
  const float* w_in = (const float*)d_in[4];
  const float* b_ir = (const float*)d_in[5];
  const float* b_iz = (const float*)d_in[6];
  const float* b_in = (const float*)d_in[7];
  const float* w_hr = (const float*)d_in[8];
  const float* w_hz = (const float*)d_in[9];
  const float* w_hn = (const float*)d_in[10];
  const float* b_hr = (const float*)d_in[11];
  const float* b_hz = (const float*)d_in[12];
  const float* b_hn = (const float*)d_in[13];
  float* out = (float*)d_out;

  cudaFuncSetAttribute(gru_rec, cudaFuncAttributeMaxDynamicSharedMemorySize, SMEM_BYTES);

  dim3 gg(NH/64, (NBATCH*NSTEP)/64, 3);
  xproj_kernel<<<gg, 256>>>(inp, w_ir, w_iz, w_in, b_ir, b_iz, b_in);

  int write_hlast = (out_size >= NBATCH*NSTEP*NH + NBATCH*NH) ? 1 : 0;
  gru_rec<<<128, 544, SMEM_BYTES>>>(h0, w_hr, w_hz, w_hn, b_hr, b_hz, b_hn,
                                    out, write_hlast);
}